// round 12
// baseline (speedup 1.0000x reference)
#include <cuda_runtime.h>
#include <cstdint>

// Geometry fixed by setup_inputs: (16, 4, 1024, 1024) float32
#define BATCH 16
#define HH 1024
#define WW 1024
#define HW (HH * WW)

#define TILE_W 128
#define TILE_H 64
#define THREADS 512

// Phase-1 T1 region: rows gy = y0-1 .. y0+64 (66), cols gx = x0-4 .. x0+131
// (34 quads of 4). Pitch 136 floats, float4-aligned.
#define P1ROWS (TILE_H + 2)        // 66
#define QPR 34                     // quads per row
#define SPITCH (QPR * 4)           // 136
#define NQUADS (P1ROWS * QPR)      // 2244
#define NITER ((NQUADS + THREADS - 1) / THREADS)   // 5

#define RED_X 128
#define NPART (RED_X * BATCH)      // 2048 partials

__device__ float g_partials[NPART];

// ---------------------------------------------------------------------------
// Stage 1: per-block max(|u|,|v|) partials (unconditional writes, no reset).
// ---------------------------------------------------------------------------
__global__ __launch_bounds__(256)
void maxabs_kernel(const float* __restrict__ in) {
    const float4* __restrict__ base =
        reinterpret_cast<const float4*>(in + (size_t)blockIdx.y * 4 * HW);
    const int n4 = 2 * HW / 4;
    float m = 0.0f;
    #pragma unroll 8
    for (int i = blockIdx.x * 256 + threadIdx.x; i < n4; i += RED_X * 256) {
        float4 vv = base[i];
        m = fmaxf(m, fabsf(vv.x));
        m = fmaxf(m, fabsf(vv.y));
        m = fmaxf(m, fabsf(vv.z));
        m = fmaxf(m, fabsf(vv.w));
    }
    #pragma unroll
    for (int o = 16; o > 0; o >>= 1)
        m = fmaxf(m, __shfl_xor_sync(0xFFFFFFFFu, m, o));
    __shared__ float smax[8];
    int lane = threadIdx.x & 31, wid = threadIdx.x >> 5;
    if (lane == 0) smax[wid] = m;
    __syncthreads();
    if (threadIdx.x == 0) {
        float mm = smax[0];
        #pragma unroll
        for (int w = 1; w < 8; w++) mm = fmaxf(mm, smax[w]);
        g_partials[blockIdx.y * RED_X + blockIdx.x] = mm;
    }
}

// ---------------------------------------------------------------------------
// Stage 2 (fused): dt reduce -> vectorized upwind advection into smem
// (edge neighbors via warp shuffle, not scalar loads) -> row-factored 9-pt
// Laplacian (vertical strips) + RaQ -> float4 out.
// ---------------------------------------------------------------------------
__global__ __launch_bounds__(THREADS)
void fused_kernel(const float* __restrict__ in, float* __restrict__ out,
                  int out_size) {
    __shared__ float sT1[P1ROWS * SPITCH];
    __shared__ float swarp[THREADS / 32];
    __shared__ float s_dt;

    const int tid = threadIdx.x;
    const int lane = tid & 31;
    const int x0 = blockIdx.x * TILE_W;
    const int y0 = blockIdx.y * TILE_H;
    const int b  = blockIdx.z;

    // ---- Prologue: reduce partials -> dt ----
    {
        float m = 0.0f;
        #pragma unroll
        for (int i = 0; i < NPART / THREADS; i++)
            m = fmaxf(m, g_partials[tid + i * THREADS]);
        #pragma unroll
        for (int o = 16; o > 0; o >>= 1)
            m = fmaxf(m, __shfl_xor_sync(0xFFFFFFFFu, m, o));
        int wid = tid >> 5;
        if (lane == 0) swarp[wid] = m;
        __syncthreads();
        if (tid == 0) {
            float mm = swarp[0];
            #pragma unroll
            for (int w = 1; w < THREADS / 32; w++) mm = fmaxf(mm, swarp[w]);
            const float dx = (float)(1.0 / 126.0);
            float dt_advect = 0.5f * 0.1f * dx / mm;
            float dx2 = dx * dx;
            float dt_diffuse = 0.5f * (dx2 * dx2) / (dx2 + dx2);
            s_dt = fminf(dt_advect, dt_diffuse);
        }
        __syncthreads();
    }
    const float dt = s_dt;

    const float dx = (float)(1.0 / 126.0);
    const float inv_dx = 1.0f / dx;

    const float* __restrict__ U  = in + (size_t)b * 4 * HW;
    const float* __restrict__ V  = U + HW;
    const float* __restrict__ T  = U + 2 * HW;
    const float* __restrict__ Ra = U + 3 * HW;

    // ---- Phase 1: advection, one float4 quad per task; horizontal
    //      neighbors come from adjacent lanes via shuffle. Fixed trip count
    //      so all 32 lanes reach the shuffles with full mask. ----
    #pragma unroll
    for (int it = 0; it < NITER; it++) {
        int q = tid + it * THREADS;
        bool act = (q < NQUADS);
        int qc = act ? q : (NQUADS - 1);    // clamp index math for idle lanes
        int ly = qc / QPR;
        int qi = qc - ly * QPR;
        int gx0 = x0 - 4 + (qi << 2);       // 4-aligned, may be -4 or 1024+
        int gy = min(max(y0 - 1 + ly, 0), HH - 1);
        int ym = max(gy - 1, 0), yp = min(gy + 1, HH - 1);
        int row = gy * WW;

        // Unconditional center-quad load. Address is always inside the
        // input allocation (worst cases spill into the V / Ra channels);
        // out-of-tile values are never consumed.
        const float4 c4 = *reinterpret_cast<const float4*>(T + row + gx0);
        // Neighbor edges: lane-1 owns quad qi-1 of the same row (its .w is
        // T[gx0-1]); lane+1 owns qi+1 (its .x is T[gx0+4]).
        float sl = __shfl_up_sync(0xFFFFFFFFu, c4.w, 1);
        float sr = __shfl_down_sync(0xFFFFFFFFu, c4.x, 1);

        if (!act) continue;

        float4 res;
        if (gx0 >= 1 && gx0 + 4 <= WW - 1) {
            bool pl = (lane > 0)  && (qi > 0);    // prev lane's c4 is valid T data
            bool pr = (lane < 31) && (qi < 33);   // next lane's c4 is valid T data
            float cl = pl ? sl : T[row + gx0 - 1];
            float cr = pr ? sr : T[row + gx0 + 4];

            const float4 t4 = *reinterpret_cast<const float4*>(T + ym * WW + gx0);
            const float4 d4 = *reinterpret_cast<const float4*>(T + yp * WW + gx0);
            const float4 u4 = *reinterpret_cast<const float4*>(U + row + gx0);
            const float4 v4 = *reinterpret_cast<const float4*>(V + row + gx0);

            float L[6] = {cl, c4.x, c4.y, c4.z, c4.w, cr};
            #pragma unroll
            for (int j = 0; j < 4; j++) {
                float c = L[j + 1];
                float u = (&u4.x)[j];
                float v = (&v4.x)[j];
                float t = (&t4.x)[j];
                float d = (&d4.x)[j];
                float dTdx = (u > 0.0f) ? (c - L[j]) * inv_dx
                                        : ((u < 0.0f) ? (L[j + 2] - c) * inv_dx : 0.0f);
                float dTdy = (v > 0.0f) ? (c - t) * inv_dx
                                        : ((v < 0.0f) ? (d - c) * inv_dx : 0.0f);
                (&res.x)[j] = c + dt * (-u * dTdx - v * dTdy);
            }
        } else {
            // Border quad (block columns at x edges): clamped scalar path.
            #pragma unroll
            for (int j = 0; j < 4; j++) {
                int gx = min(max(gx0 + j, 0), WW - 1);
                int xm = max(gx - 1, 0), xp = min(gx + 1, WW - 1);
                float c = T[row + gx];
                float l = T[row + xm];
                float r = T[row + xp];
                float t = T[ym * WW + gx];
                float d = T[yp * WW + gx];
                float u = U[row + gx];
                float v = V[row + gx];
                float dTdx = (u > 0.0f) ? (c - l) * inv_dx
                                        : ((u < 0.0f) ? (r - c) * inv_dx : 0.0f);
                float dTdy = (v > 0.0f) ? (c - t) * inv_dx
                                        : ((v < 0.0f) ? (d - c) * inv_dx : 0.0f);
                (&res.x)[j] = c + dt * (-u * dTdx - v * dTdy);
            }
        }
        *reinterpret_cast<float4*>(&sT1[ly * SPITCH + (qi << 2)]) = res;
    }
    __syncthreads();

    // ---- Phase 2: row-factored 9-pt Laplacian, vertical 4-row strips ----
    // lap = H(top) + 2*H(mid) + H(bot) - 16*center, H(row)=x+2y+z per column.
    {
        const float dx2 = dx * dx;
        const float lap_scale = 0.25f / dx2;
        const int cx = tid & 31;
        const int cy = tid >> 5;          // 0..15
        const int qx = cx << 2;           // 0..124
        const int qy0 = cy << 2;          // 0..60

        // Prefetch Ra for the 4 output rows (independent LDG.128s).
        float4 ra[4];
        #pragma unroll
        for (int r = 0; r < 4; r++)
            ra[r] = *reinterpret_cast<const float4*>(
                Ra + (size_t)(y0 + qy0 + r) * WW + (x0 + qx));

        float* outb = out + (size_t)b * HW;

        float h_m2[4], h_m1[4], c_m1[4];
        #pragma unroll
        for (int i = 0; i < 6; i++) {
            const float* s = &sT1[(qy0 + i) * SPITCH + qx];
            float rr[12];
            *reinterpret_cast<float4*>(&rr[0]) =
                *reinterpret_cast<const float4*>(s);
            *reinterpret_cast<float4*>(&rr[4]) =
                *reinterpret_cast<const float4*>(s + 4);
            *reinterpret_cast<float4*>(&rr[8]) =
                *reinterpret_cast<const float4*>(s + 8);

            float h[4], c[4];
            #pragma unroll
            for (int jj = 0; jj < 4; jj++) {
                h[jj] = rr[jj + 3] + 2.0f * rr[jj + 4] + rr[jj + 5];
                c[jj] = rr[jj + 4];
            }

            if (i >= 2) {
                int oy = qy0 + i - 2;
                float4 res;
                #pragma unroll
                for (int jj = 0; jj < 4; jj++) {
                    float lap = h_m2[jj] + 2.0f * h_m1[jj] + h[jj]
                              - 16.0f * c_m1[jj];
                    (&res.x)[jj] = c_m1[jj]
                        + dt * (lap_scale * lap + (&ra[i - 2].x)[jj]);
                }
                *reinterpret_cast<float4*>(
                    outb + (size_t)(y0 + oy) * WW + (x0 + qx)) = res;
            }
            #pragma unroll
            for (int jj = 0; jj < 4; jj++) {
                h_m2[jj] = h_m1[jj];
                h_m1[jj] = h[jj];
                c_m1[jj] = c[jj];
            }
        }
    }

    if (tid == 0 && blockIdx.x == 0 && blockIdx.y == 0 && blockIdx.z == 0) {
        out[out_size - 1] = dt;
    }
}

extern "C" void kernel_launch(void* const* d_in, const int* in_sizes, int n_in,
                              void* d_out, int out_size) {
    const float* in = (const float*)d_in[0];
    float* out = (float*)d_out;

    dim3 rgrid(RED_X, BATCH);
    maxabs_kernel<<<rgrid, 256>>>(in);

    dim3 fgrid(WW / TILE_W, HH / TILE_H, BATCH);  // 8 x 16 x 16 = 2048
    fused_kernel<<<fgrid, THREADS>>>(in, out, out_size);
}

// round 13
// speedup vs baseline: 1.2295x; 1.2295x over previous
#include <cuda_runtime.h>
#include <cstdint>

// Geometry fixed by setup_inputs: (16, 4, 1024, 1024) float32
#define BATCH 16
#define HH 1024
#define WW 1024
#define HW (HH * WW)

#define TILE_W 128
#define TILE_H 64
#define THREADS 512

// Phase-1 T1 region: rows gy = y0-1 .. y0+64 (66), cols gx = x0-4 .. x0+131
// (34 quads of 4). Pitch 136 floats, float4-aligned.
#define P1ROWS (TILE_H + 2)        // 66
#define QPR 34                     // quads per row
#define SPITCH (QPR * 4)           // 136
#define NQUADS (P1ROWS * QPR)      // 2244

#define RED_X 128
#define NPART (RED_X * BATCH)      // 2048 partials

__device__ float g_partials[NPART];

// ---------------------------------------------------------------------------
// Stage 1: per-block max(|u|,|v|) partials (unconditional writes, no reset).
// ---------------------------------------------------------------------------
__global__ __launch_bounds__(256)
void maxabs_kernel(const float* __restrict__ in) {
    const float4* __restrict__ base =
        reinterpret_cast<const float4*>(in + (size_t)blockIdx.y * 4 * HW);
    const int n4 = 2 * HW / 4;
    float m = 0.0f;
    #pragma unroll 8
    for (int i = blockIdx.x * 256 + threadIdx.x; i < n4; i += RED_X * 256) {
        float4 vv = base[i];
        m = fmaxf(m, fabsf(vv.x));
        m = fmaxf(m, fabsf(vv.y));
        m = fmaxf(m, fabsf(vv.z));
        m = fmaxf(m, fabsf(vv.w));
    }
    #pragma unroll
    for (int o = 16; o > 0; o >>= 1)
        m = fmaxf(m, __shfl_xor_sync(0xFFFFFFFFu, m, o));
    __shared__ float smax[8];
    int lane = threadIdx.x & 31, wid = threadIdx.x >> 5;
    if (lane == 0) smax[wid] = m;
    __syncthreads();
    if (threadIdx.x == 0) {
        float mm = smax[0];
        #pragma unroll
        for (int w = 1; w < 8; w++) mm = fmaxf(mm, smax[w]);
        g_partials[blockIdx.y * RED_X + blockIdx.x] = mm;
    }
}

// ---------------------------------------------------------------------------
// Stage 2 (fused): dt reduce -> vectorized upwind advection into smem
// -> row-factored 9-pt Laplacian (vertical strips; edge floats via warp
// shuffle: 1 LDS.128/row instead of 3) + RaQ -> float4 out.
// __launch_bounds__(512,3): pin 3 blocks/SM (regs <= 42, no spill expected).
// ---------------------------------------------------------------------------
__global__ __launch_bounds__(THREADS, 3)
void fused_kernel(const float* __restrict__ in, float* __restrict__ out,
                  int out_size) {
    __shared__ float sT1[P1ROWS * SPITCH];
    __shared__ float swarp[THREADS / 32];
    __shared__ float s_dt;

    const int tid = threadIdx.x;
    const int x0 = blockIdx.x * TILE_W;
    const int y0 = blockIdx.y * TILE_H;
    const int b  = blockIdx.z;

    // ---- Prologue: reduce partials -> dt ----
    {
        float m = 0.0f;
        #pragma unroll
        for (int i = 0; i < NPART / THREADS; i++)
            m = fmaxf(m, g_partials[tid + i * THREADS]);
        #pragma unroll
        for (int o = 16; o > 0; o >>= 1)
            m = fmaxf(m, __shfl_xor_sync(0xFFFFFFFFu, m, o));
        int lane = tid & 31, wid = tid >> 5;
        if (lane == 0) swarp[wid] = m;
        __syncthreads();
        if (tid == 0) {
            float mm = swarp[0];
            #pragma unroll
            for (int w = 1; w < THREADS / 32; w++) mm = fmaxf(mm, swarp[w]);
            const float dx = (float)(1.0 / 126.0);
            float dt_advect = 0.5f * 0.1f * dx / mm;
            float dx2 = dx * dx;
            float dt_diffuse = 0.5f * (dx2 * dx2) / (dx2 + dx2);
            s_dt = fminf(dt_advect, dt_diffuse);
        }
        __syncthreads();
    }
    const float dt = s_dt;

    const float dx = (float)(1.0 / 126.0);
    const float inv_dx = 1.0f / dx;

    const float* __restrict__ U  = in + (size_t)b * 4 * HW;
    const float* __restrict__ V  = U + HW;
    const float* __restrict__ T  = U + 2 * HW;
    const float* __restrict__ Ra = U + 3 * HW;

    // ---- Phase 1: advection, one float4 quad per iteration (R7 form) ----
    for (int q = tid; q < NQUADS; q += THREADS) {
        int ly = q / QPR;                   // 0..65
        int qi = q - ly * QPR;              // 0..33
        int gx0 = x0 - 4 + (qi << 2);       // quad's first gx (4-aligned)
        int gy = min(max(y0 - 1 + ly, 0), HH - 1);
        int ym = max(gy - 1, 0), yp = min(gy + 1, HH - 1);
        int row = gy * WW;

        float4 res;
        if (gx0 >= 1 && gx0 + 4 <= WW - 1) {
            const float4 c4 = *reinterpret_cast<const float4*>(T + row + gx0);
            const float4 t4 = *reinterpret_cast<const float4*>(T + ym * WW + gx0);
            const float4 d4 = *reinterpret_cast<const float4*>(T + yp * WW + gx0);
            const float4 u4 = *reinterpret_cast<const float4*>(U + row + gx0);
            const float4 v4 = *reinterpret_cast<const float4*>(V + row + gx0);
            float cl = T[row + gx0 - 1];
            float cr = T[row + gx0 + 4];

            float L[6] = {cl, c4.x, c4.y, c4.z, c4.w, cr};
            #pragma unroll
            for (int j = 0; j < 4; j++) {
                float c = L[j + 1];
                float u = (&u4.x)[j];
                float v = (&v4.x)[j];
                float t = (&t4.x)[j];
                float d = (&d4.x)[j];
                float dTdx = (u > 0.0f) ? (c - L[j]) * inv_dx
                                        : ((u < 0.0f) ? (L[j + 2] - c) * inv_dx : 0.0f);
                float dTdy = (v > 0.0f) ? (c - t) * inv_dx
                                        : ((v < 0.0f) ? (d - c) * inv_dx : 0.0f);
                (&res.x)[j] = c + dt * (-u * dTdx - v * dTdy);
            }
        } else {
            #pragma unroll
            for (int j = 0; j < 4; j++) {
                int gx = min(max(gx0 + j, 0), WW - 1);
                int xm = max(gx - 1, 0), xp = min(gx + 1, WW - 1);
                float c = T[row + gx];
                float l = T[row + xm];
                float r = T[row + xp];
                float t = T[ym * WW + gx];
                float d = T[yp * WW + gx];
                float u = U[row + gx];
                float v = V[row + gx];
                float dTdx = (u > 0.0f) ? (c - l) * inv_dx
                                        : ((u < 0.0f) ? (r - c) * inv_dx : 0.0f);
                float dTdy = (v > 0.0f) ? (c - t) * inv_dx
                                        : ((v < 0.0f) ? (d - c) * inv_dx : 0.0f);
                (&res.x)[j] = c + dt * (-u * dTdx - v * dTdy);
            }
        }
        *reinterpret_cast<float4*>(&sT1[ly * SPITCH + (qi << 2)]) = res;
    }
    __syncthreads();

    // ---- Phase 2: row-factored 9-pt Laplacian, vertical 4-row strips.
    //      Per smem row: one aligned LDS.128 of the center quad; the two
    //      edge floats come from adjacent lanes via shuffle (lane N's left
    //      edge = lane N-1's m.w, right edge = lane N+1's m.x). Lanes 0/31
    //      patch from smem (cols 3 / 132 exist in the padded halo row). ----
    {
        const float dx2 = dx * dx;
        const float lap_scale = 0.25f / dx2;
        const int lane = tid & 31;        // == cx: quad column
        const int cy = tid >> 5;          // 0..15
        const int qx = lane << 2;         // 0..124
        const int qy0 = cy << 2;          // 0..60

        // Prefetch Ra for the 4 output rows (independent LDG.128s).
        float4 ra[4];
        #pragma unroll
        for (int r = 0; r < 4; r++)
            ra[r] = *reinterpret_cast<const float4*>(
                Ra + (size_t)(y0 + qy0 + r) * WW + (x0 + qx));

        float* outb = out + (size_t)b * HW;

        float h_m2[4], h_m1[4], c_m1[4];
        #pragma unroll
        for (int i = 0; i < 6; i++) {
            const float* srow = &sT1[(qy0 + i) * SPITCH];
            // Center quad: smem cols qx+4 .. qx+7 (window is cols qx+3..qx+8).
            float4 m = *reinterpret_cast<const float4*>(srow + qx + 4);
            float le = __shfl_up_sync(0xFFFFFFFFu, m.w, 1);
            float re = __shfl_down_sync(0xFFFFFFFFu, m.x, 1);
            if (lane == 0)  le = srow[3];        // left halo quad's .w
            if (lane == 31) re = srow[132];      // right halo quad's .x

            float h[4];
            h[0] = le  + 2.0f * m.x + m.y;
            h[1] = m.x + 2.0f * m.y + m.z;
            h[2] = m.y + 2.0f * m.z + m.w;
            h[3] = m.z + 2.0f * m.w + re;

            if (i >= 2) {
                int oy = qy0 + i - 2;
                float4 res;
                #pragma unroll
                for (int jj = 0; jj < 4; jj++) {
                    float lap = h_m2[jj] + 2.0f * h_m1[jj] + h[jj]
                              - 16.0f * c_m1[jj];
                    (&res.x)[jj] = c_m1[jj]
                        + dt * (lap_scale * lap + (&ra[i - 2].x)[jj]);
                }
                *reinterpret_cast<float4*>(
                    outb + (size_t)(y0 + oy) * WW + (x0 + qx)) = res;
            }
            #pragma unroll
            for (int jj = 0; jj < 4; jj++) {
                h_m2[jj] = h_m1[jj];
                h_m1[jj] = h[jj];
            }
            c_m1[0] = m.x; c_m1[1] = m.y; c_m1[2] = m.z; c_m1[3] = m.w;
        }
    }

    if (tid == 0 && blockIdx.x == 0 && blockIdx.y == 0 && blockIdx.z == 0) {
        out[out_size - 1] = dt;
    }
}

extern "C" void kernel_launch(void* const* d_in, const int* in_sizes, int n_in,
                              void* d_out, int out_size) {
    const float* in = (const float*)d_in[0];
    float* out = (float*)d_out;

    dim3 rgrid(RED_X, BATCH);
    maxabs_kernel<<<rgrid, 256>>>(in);

    dim3 fgrid(WW / TILE_W, HH / TILE_H, BATCH);  // 8 x 16 x 16 = 2048
    fused_kernel<<<fgrid, THREADS>>>(in, out, out_size);
}